// round 14
// baseline (speedup 1.0000x reference)
#include <cuda_runtime.h>
#include <cuda_fp16.h>
#include <cstddef>

// Problem: B=2, H=16, T=2048, C=64
#define T_SEQ   2048
#define CDIM    64
#define HEADS   16
#define BATCH   2
#define M_TILE  32
#define KTILE   128
#define ROUNDS  (T_SEQ/KTILE)    // 16
#define THREADS 512
#define KVSTR   72               // halves per staged K/V row (pad)
#define PSTR    68               // floats per partial-out row (pad)
#define KVELEMS (BATCH*HEADS*T_SEQ*CDIM)             // 4,194,304
#define MASK_ELEMS (BATCH*T_SEQ*T_SEQ)               // 8,388,608
#define MBITS_WORDS (MASK_ELEMS/32)                  // 262,144 (1 MB)

// fp16 copies of K and V (prologue fills these)
__device__ __half g_k16[KVELEMS];
__device__ __half g_v16[KVELEMS];
// bit-packed mask: word w holds mask elems [w*32, w*32+32), bit c = (mask!=0)
__device__ unsigned g_mbits[MBITS_WORDS];

#define KVBUF_BYTES (KTILE*KVSTR*2)            // 18432
#define OFF_V       (2*KVBUF_BYTES)            // 36864
#define OFF_QH      (4*KVBUF_BYTES)            // 73728
#define OFF_RED     (OFF_QH + M_TILE*KVSTR*2)  // 78336
#define OFF_RINV    (OFF_RED + 16*16*4)        // 79360
#define SMEM_BYTES  (OFF_RINV + 128)           // 79488 -> 2 CTAs/SM

__device__ __forceinline__ unsigned pk2f(float a, float b) {
    __half2 h = __floats2half2_rn(a, b);
    return *(unsigned*)&h;
}
__device__ __forceinline__ void ldsm_x4(unsigned &r0, unsigned &r1, unsigned &r2,
                                        unsigned &r3, unsigned addr) {
    asm volatile("ldmatrix.sync.aligned.m8n8.x4.shared.b16 {%0,%1,%2,%3}, [%4];"
                 : "=r"(r0), "=r"(r1), "=r"(r2), "=r"(r3) : "r"(addr));
}
__device__ __forceinline__ void ldsm_x4_t(unsigned &r0, unsigned &r1, unsigned &r2,
                                          unsigned &r3, unsigned addr) {
    asm volatile("ldmatrix.sync.aligned.m8n8.x4.trans.shared.b16 {%0,%1,%2,%3}, [%4];"
                 : "=r"(r0), "=r"(r1), "=r"(r2), "=r"(r3) : "r"(addr));
}
__device__ __forceinline__ void mma_f16(float &d0, float &d1, float &d2, float &d3,
                                        unsigned a0, unsigned a1, unsigned a2, unsigned a3,
                                        unsigned b0, unsigned b1) {
    asm volatile("mma.sync.aligned.m16n8k16.row.col.f32.f16.f16.f32 "
                 "{%0,%1,%2,%3},{%4,%5,%6,%7},{%8,%9},{%0,%1,%2,%3};"
                 : "+f"(d0), "+f"(d1), "+f"(d2), "+f"(d3)
                 : "r"(a0), "r"(a1), "r"(a2), "r"(a3), "r"(b0), "r"(b1));
}
#define CP_COMMIT()  asm volatile("cp.async.commit_group;" ::: "memory")
#define CP_WAIT0()   asm volatile("cp.async.wait_group 0;" ::: "memory")
__device__ __forceinline__ void cp16(void* smem_dst, const void* gsrc) {
    unsigned saddr = (unsigned)__cvta_generic_to_shared(smem_dst);
    asm volatile("cp.async.cg.shared.global [%0], [%1], 16;" :: "r"(saddr), "l"(gsrc) : "memory");
}
// stage one 128x64 fp16 tile from global fp16 into padded smem (stride KVSTR)
__device__ __forceinline__ void stage_one(__half* dst, const __half* gsrc, int t) {
    #pragma unroll
    for (int i = 0; i < 2; i++) {
        int c = t + i * THREADS;
        int row = c >> 3, seg = c & 7;
        cp16(&dst[row * KVSTR + seg * 8], &gsrc[row * CDIM + seg * 8]);
    }
}

// ---- prologue 1: fp32 K,V -> fp16 ----
__global__ __launch_bounds__(512) void cvt_kernel(const float4* __restrict__ k,
                                                  const float4* __restrict__ v) {
    int i = blockIdx.x * 512 + threadIdx.x;
    float4 a = k[i];
    float4 b = v[i];
    ((uint2*)g_k16)[i] = make_uint2(pk2f(a.x, a.y), pk2f(a.z, a.w));
    ((uint2*)g_v16)[i] = make_uint2(pk2f(b.x, b.y), pk2f(b.z, b.w));
}
// ---- prologue 2: mask -> bitmask ----
__global__ __launch_bounds__(512) void pack_mask_kernel(const int* __restrict__ mask) {
    int i = blockIdx.x * 512 + threadIdx.x;
    unsigned bal = __ballot_sync(0xffffffffu, mask[i] != 0);
    if ((threadIdx.x & 31) == 0) g_mbits[i >> 5] = bal;
}

__global__ __launch_bounds__(THREADS, 2)
void sdpa_kernel(const float* __restrict__ q,
                 float* __restrict__ out,
                 float* __restrict__ attn)
{
    extern __shared__ char smc[];
    __half* kvbK = (__half*)smc;
    __half* kvbV = (__half*)(smc + OFF_V);
    __half* qh   = (__half*)(smc + OFF_QH);
    float*  red  = (float*)(smc + OFF_RED);
    float*  rinv = (float*)(smc + OFF_RINV);
    const unsigned sbase = (unsigned)__cvta_generic_to_shared(smc);

    const int t    = threadIdx.x;
    const int lane = t & 31;
    const int w    = t >> 5;
    const int mb   = w & 1;           // 16-row block
    const int jg   = w >> 1;          // 0..7: 16-col j slice per round
    const int m0   = blockIdx.x * M_TILE;
    const int h    = blockIdx.y;
    const int b    = blockIdx.z;
    const int bh   = b * HEADS + h;

    const float4* qg4 = (const float4*)(q + ((size_t)bh * T_SEQ + m0) * CDIM);
    const __half* kg  = g_k16 + (size_t)bh * T_SEQ * CDIM;
    const __half* vg  = g_v16 + (size_t)bh * T_SEQ * CDIM;
    float* attng = attn + ((size_t)bh * T_SEQ + m0) * T_SEQ;
    float* outg  = out  + ((size_t)bh * T_SEQ + m0) * CDIM;

    // ---- stage K tile 0 ----
    stage_one(kvbK, kg, t);
    CP_COMMIT();

    // ---- Q load (scaled 1/8) -> fp16 smem ----
    {
        int row = t >> 4, c4 = t & 15;
        float4 f = qg4[t];
        *(uint2*)&qh[row * KVSTR + c4 * 4] =
            make_uint2(pk2f(f.x * 0.125f, f.y * 0.125f), pk2f(f.z * 0.125f, f.w * 0.125f));
    }
    __syncthreads();   // qh visible

    // ---- Q A-fragments for this warp's 16-row block ----
    unsigned qa[4][4];
    {
        int rsel = lane & 15, csel = (lane >> 4) & 1;
        #pragma unroll
        for (int ks = 0; ks < 4; ks++) {
            unsigned addr = sbase + OFF_QH +
                (unsigned)((mb * 16 + rsel) * KVSTR + ks * 16 + csel * 8) * 2;
            ldsm_x4(qa[ks][0], qa[ks][1], qa[ks][2], qa[ks][3], addr);
        }
    }

    const int iL = lane & 7, subL = lane >> 3;
    const int gq = lane >> 2, t2 = (lane & 3) * 2;
    const int rowA = mb * 16 + gq;
    const unsigned* mwA = g_mbits + ((size_t)b * T_SEQ + m0 + rowA) * (T_SEQ / 32);
    const unsigned* mwB = mwA + 8 * (T_SEQ / 32);
    const int jgh    = jg >> 1;
    const int bpbase = (jg & 1) * 16 + t2;

    float rs0 = 0.f, rs1 = 0.f;

    // ================= Pass A: rowsums only (K staging, no stores) =================
    #pragma unroll 1
    for (int r = 0; r < ROUNDS; r++) {
        CP_WAIT0();
        __syncthreads();
        const unsigned mw0 = mwA[r * 4 + jgh];
        const unsigned mw1 = mwB[r * 4 + jgh];
        if (r + 1 < ROUNDS) {
            stage_one(kvbK + ((r + 1) & 1) * (KTILE * KVSTR),
                      kg + (size_t)(r + 1) * (KTILE * CDIM), t);
            CP_COMMIT();
        }

        const unsigned kb = sbase + (r & 1) * KVBUF_BYTES;
        float d[2][4] = {{0.f,0.f,0.f,0.f},{0.f,0.f,0.f,0.f}};
        #pragma unroll
        for (int nt = 0; nt < 2; nt++) {
            unsigned bb[2][4];
            #pragma unroll
            for (int s = 0; s < 2; s++) {
                unsigned addr = kb +
                    (unsigned)((jg * 16 + nt * 8 + iL) * KVSTR + s * 32 + subL * 8) * 2;
                ldsm_x4(bb[s][0], bb[s][1], bb[s][2], bb[s][3], addr);
            }
            mma_f16(d[nt][0], d[nt][1], d[nt][2], d[nt][3],
                    qa[0][0], qa[0][1], qa[0][2], qa[0][3], bb[0][0], bb[0][1]);
            mma_f16(d[nt][0], d[nt][1], d[nt][2], d[nt][3],
                    qa[1][0], qa[1][1], qa[1][2], qa[1][3], bb[0][2], bb[0][3]);
            mma_f16(d[nt][0], d[nt][1], d[nt][2], d[nt][3],
                    qa[2][0], qa[2][1], qa[2][2], qa[2][3], bb[1][0], bb[1][1]);
            mma_f16(d[nt][0], d[nt][1], d[nt][2], d[nt][3],
                    qa[3][0], qa[3][1], qa[3][2], qa[3][3], bb[1][2], bb[1][3]);
        }
        #pragma unroll
        for (int nt = 0; nt < 2; nt++) {
            const int bp = bpbase + nt * 8;
            if ((mw0 >> bp) & 1u)       rs0 += __expf(d[nt][0]);
            if ((mw0 >> (bp + 1)) & 1u) rs0 += __expf(d[nt][1]);
            if ((mw1 >> bp) & 1u)       rs1 += __expf(d[nt][2]);
            if ((mw1 >> (bp + 1)) & 1u) rs1 += __expf(d[nt][3]);
        }
    }

    // ---- rowsum reduce -> rinv ----
    rs0 += __shfl_xor_sync(0xffffffffu, rs0, 1);
    rs0 += __shfl_xor_sync(0xffffffffu, rs0, 2);
    rs1 += __shfl_xor_sync(0xffffffffu, rs1, 1);
    rs1 += __shfl_xor_sync(0xffffffffu, rs1, 2);
    if ((lane & 3) == 0) {
        red[w * 16 + gq]     = rs0;
        red[w * 16 + gq + 8] = rs1;
    }
    __syncthreads();   // red visible; pass-A K bufs dead
    if (t < 32) {
        int mbr = t >> 4, rl = t & 15;
        float s = 0.f;
        #pragma unroll
        for (int g = 0; g < 8; g++) s += red[(g * 2 + mbr) * 16 + rl];
        rinv[t] = 1.0f / s;
    }
    // stage pass-B tile 0 (K+V)
    stage_one(kvbK, kg, t);
    stage_one(kvbV, vg, t);
    CP_COMMIT();
    __syncthreads();   // rinv visible
    const float ri0 = rinv[rowA];
    const float ri1 = rinv[rowA + 8];

    float acc[8][4];
    #pragma unroll
    for (int nn = 0; nn < 8; nn++)
        #pragma unroll
        for (int d = 0; d < 4; d++) acc[nn][d] = 0.f;

    // ================= Pass B: recompute S, write attn, P@V =================
    #pragma unroll 1
    for (int r = 0; r < ROUNDS; r++) {
        CP_WAIT0();
        __syncthreads();
        const unsigned mw0 = mwA[r * 4 + jgh];
        const unsigned mw1 = mwB[r * 4 + jgh];
        if (r + 1 < ROUNDS) {
            stage_one(kvbK + ((r + 1) & 1) * (KTILE * KVSTR),
                      kg + (size_t)(r + 1) * (KTILE * CDIM), t);
            stage_one(kvbV + ((r + 1) & 1) * (KTILE * KVSTR),
                      vg + (size_t)(r + 1) * (KTILE * CDIM), t);
            CP_COMMIT();
        }

        const int jbase = r * KTILE + jg * 16;
        const unsigned kb = sbase + (r & 1) * KVBUF_BYTES;
        float d[2][4] = {{0.f,0.f,0.f,0.f},{0.f,0.f,0.f,0.f}};
        #pragma unroll
        for (int nt = 0; nt < 2; nt++) {
            unsigned bb[2][4];
            #pragma unroll
            for (int s = 0; s < 2; s++) {
                unsigned addr = kb +
                    (unsigned)((jg * 16 + nt * 8 + iL) * KVSTR + s * 32 + subL * 8) * 2;
                ldsm_x4(bb[s][0], bb[s][1], bb[s][2], bb[s][3], addr);
            }
            mma_f16(d[nt][0], d[nt][1], d[nt][2], d[nt][3],
                    qa[0][0], qa[0][1], qa[0][2], qa[0][3], bb[0][0], bb[0][1]);
            mma_f16(d[nt][0], d[nt][1], d[nt][2], d[nt][3],
                    qa[1][0], qa[1][1], qa[1][2], qa[1][3], bb[0][2], bb[0][3]);
            mma_f16(d[nt][0], d[nt][1], d[nt][2], d[nt][3],
                    qa[2][0], qa[2][1], qa[2][2], qa[2][3], bb[1][0], bb[1][1]);
            mma_f16(d[nt][0], d[nt][1], d[nt][2], d[nt][3],
                    qa[3][0], qa[3][1], qa[3][2], qa[3][3], bb[1][2], bb[1][3]);
        }

        // ---- mask + exp + NORMALIZE + direct attn fp32 store + P frags ----
        unsigned pa[4];
        #pragma unroll
        for (int nt = 0; nt < 2; nt++) {
            const int bp = bpbase + nt * 8;
            float e0 = ((mw0 >> bp) & 1u)       ? __expf(d[nt][0]) * ri0 : 0.f;
            float e1 = ((mw0 >> (bp + 1)) & 1u) ? __expf(d[nt][1]) * ri0 : 0.f;
            float e2 = ((mw1 >> bp) & 1u)       ? __expf(d[nt][2]) * ri1 : 0.f;
            float e3 = ((mw1 >> (bp + 1)) & 1u) ? __expf(d[nt][3]) * ri1 : 0.f;
            *(float2*)&attng[(size_t)rowA * T_SEQ + jbase + nt * 8 + t2] =
                make_float2(e0, e1);
            *(float2*)&attng[(size_t)(rowA + 8) * T_SEQ + jbase + nt * 8 + t2] =
                make_float2(e2, e3);
            pa[nt * 2]     = pk2f(e0, e1);   // normalized P fragments
            pa[nt * 2 + 1] = pk2f(e2, e3);
        }

        // ---- P @ V : 8 k16 mma into persistent acc (P already normalized) ----
        const unsigned vb = sbase + OFF_V + (r & 1) * KVBUF_BYTES;
        #pragma unroll
        for (int cb = 0; cb < 4; cb++) {
            unsigned v0, v1, v2, v3;
            unsigned addr = vb +
                (unsigned)((jg * 16 + (lane & 15)) * KVSTR + cb * 16 + ((lane >> 4) & 1) * 8) * 2;
            ldsm_x4_t(v0, v1, v2, v3, addr);
            mma_f16(acc[cb * 2][0], acc[cb * 2][1], acc[cb * 2][2], acc[cb * 2][3],
                    pa[0], pa[1], pa[2], pa[3], v0, v1);
            mma_f16(acc[cb * 2 + 1][0], acc[cb * 2 + 1][1], acc[cb * 2 + 1][2], acc[cb * 2 + 1][3],
                    pa[0], pa[1], pa[2], pa[3], v2, v3);
        }
    }

    // ---- out partials into smem (reuse K/V buf region) ----
    __syncthreads();   // all smem K/V reads done
    float* part = (float*)smc;   // [8 jg][32 rows][PSTR]
    #pragma unroll
    for (int nn = 0; nn < 8; nn++) {
        int col = nn * 8 + t2;
        *(float2*)&part[jg * (32 * PSTR) + rowA * PSTR + col] =
            make_float2(acc[nn][0], acc[nn][1]);
        *(float2*)&part[jg * (32 * PSTR) + (rowA + 8) * PSTR + col] =
            make_float2(acc[nn][2], acc[nn][3]);
    }
    __syncthreads();

    // ---- out: 32 rows x 16 c4 = 512 float4, one per thread (no rinv: P normalized) ----
    {
        int row = t >> 4, c4 = t & 15;
        float4 s = {0.f, 0.f, 0.f, 0.f};
        #pragma unroll
        for (int g = 0; g < 8; g++) {
            float4 p = *(float4*)&part[g * (32 * PSTR) + row * PSTR + c4 * 4];
            s.x += p.x; s.y += p.y; s.z += p.z; s.w += p.w;
        }
        ((float4*)outg)[row * 16 + c4] = s;
    }
}

extern "C" void kernel_launch(void* const* d_in, const int* in_sizes, int n_in,
                              void* d_out, int out_size)
{
    const float* q    = (const float*)d_in[0];
    const float* k    = (const float*)d_in[1];
    const float* v    = (const float*)d_in[2];
    const int*   mask = (const int*)d_in[3];

    float* out  = (float*)d_out;                                   // [B,H,T,C]
    float* attn = out + (size_t)BATCH * HEADS * T_SEQ * CDIM;      // [B,H,T,T]

    // prologues: K,V -> fp16; mask -> bits
    cvt_kernel<<<KVELEMS / 4 / 512, 512>>>((const float4*)k, (const float4*)v);
    pack_mask_kernel<<<MASK_ELEMS / 512, 512>>>(mask);

    cudaFuncSetAttribute(sdpa_kernel,
                         cudaFuncAttributeMaxDynamicSharedMemorySize, SMEM_BYTES);
    dim3 grid(T_SEQ / M_TILE, HEADS, BATCH);   // (64, 16, 2)
    sdpa_kernel<<<grid, THREADS, SMEM_BYTES>>>(q, out, attn);
}

// round 16
// speedup vs baseline: 1.1089x; 1.1089x over previous
#include <cuda_runtime.h>
#include <cuda_fp16.h>
#include <cstddef>

// Problem: B=2, H=16, T=2048, C=64
#define T_SEQ   2048
#define CDIM    64
#define HEADS   16
#define BATCH   2
#define M_TILE  32
#define KTILE   128
#define ROUNDS  (T_SEQ/KTILE)    // 16
#define THREADS 512
#define PSTR    68               // floats per partial-out row (pad)
#define KVELEMS (BATCH*HEADS*T_SEQ*CDIM)
#define MASK_ELEMS (BATCH*T_SEQ*T_SEQ)
#define SCO_ELEMS ((size_t)BATCH*HEADS*T_SEQ*T_SEQ)

__device__ __half   g_k16[KVELEMS];
__device__ __half   g_v16[KVELEMS];
__device__ unsigned g_mbits[MASK_ELEMS/32];
__device__ __half   g_sco[SCO_ELEMS];    // unnormalized exp scratch, warp-native

// smem: pair slices 8*9216=73728 | qh 32*72*2=4608 | red 1024 | rinv 128
#define PAIR_BYTES 9216                   // Kbuf0,Kbuf1,Vbuf0,Vbuf1 each 16x72 halves
#define OFF_QH     73728
#define OFF_RED    78336
#define OFF_RINV   79360
#define SMEM_BYTES 79488                  // -> 2 CTAs/SM

__device__ __forceinline__ unsigned pk2f(float a, float b) {
    __half2 h = __floats2half2_rn(a, b);
    return *(unsigned*)&h;
}
__device__ __forceinline__ void ldsm_x4(unsigned &r0, unsigned &r1, unsigned &r2,
                                        unsigned &r3, unsigned addr) {
    asm volatile("ldmatrix.sync.aligned.m8n8.x4.shared.b16 {%0,%1,%2,%3}, [%4];"
                 : "=r"(r0), "=r"(r1), "=r"(r2), "=r"(r3) : "r"(addr));
}
__device__ __forceinline__ void ldsm_x4_t(unsigned &r0, unsigned &r1, unsigned &r2,
                                          unsigned &r3, unsigned addr) {
    asm volatile("ldmatrix.sync.aligned.m8n8.x4.trans.shared.b16 {%0,%1,%2,%3}, [%4];"
                 : "=r"(r0), "=r"(r1), "=r"(r2), "=r"(r3) : "r"(addr));
}
__device__ __forceinline__ void mma_f16(float &d0, float &d1, float &d2, float &d3,
                                        unsigned a0, unsigned a1, unsigned a2, unsigned a3,
                                        unsigned b0, unsigned b1) {
    asm volatile("mma.sync.aligned.m16n8k16.row.col.f32.f16.f16.f32 "
                 "{%0,%1,%2,%3},{%4,%5,%6,%7},{%8,%9},{%0,%1,%2,%3};"
                 : "+f"(d0), "+f"(d1), "+f"(d2), "+f"(d3)
                 : "r"(a0), "r"(a1), "r"(a2), "r"(a3), "r"(b0), "r"(b1));
}
#define CP_COMMIT() asm volatile("cp.async.commit_group;" ::: "memory")
#define CP_WAIT1()  asm volatile("cp.async.wait_group 1;" ::: "memory")
#define CP_WAIT0()  asm volatile("cp.async.wait_group 0;" ::: "memory")
#define BARP(id)    asm volatile("bar.sync %0, 64;" :: "r"(id) : "memory")
__device__ __forceinline__ void cp16(unsigned s, const void* g) {
    asm volatile("cp.async.cg.shared.global [%0], [%1], 16;" :: "r"(s), "l"(g) : "memory");
}
// pair-private staging: 16 rows x 64 halves for K and V (2 chunks each per thread)
__device__ __forceinline__ void stage_pair(unsigned dk, unsigned dv,
                                           const __half* sk, const __half* sv, int tp) {
    #pragma unroll
    for (int i = 0; i < 2; i++) {
        int c = tp + i * 64;              // 0..127 chunks of 16B
        int row = c >> 3, seg = c & 7;
        cp16(dk + (unsigned)(row * 144 + seg * 16), sk + row * CDIM + seg * 8);
        cp16(dv + (unsigned)(row * 144 + seg * 16), sv + row * CDIM + seg * 8);
    }
}

__global__ __launch_bounds__(512) void cvt_kernel(const float4* __restrict__ k,
                                                  const float4* __restrict__ v) {
    int i = blockIdx.x * 512 + threadIdx.x;
    float4 a = k[i];
    float4 b = v[i];
    ((uint2*)g_k16)[i] = make_uint2(pk2f(a.x, a.y), pk2f(a.z, a.w));
    ((uint2*)g_v16)[i] = make_uint2(pk2f(b.x, b.y), pk2f(b.z, b.w));
}
__global__ __launch_bounds__(512) void pack_mask_kernel(const int* __restrict__ mask) {
    int i = blockIdx.x * 512 + threadIdx.x;
    unsigned bal = __ballot_sync(0xffffffffu, mask[i] != 0);
    if ((threadIdx.x & 31) == 0) g_mbits[i >> 5] = bal;
}

__global__ __launch_bounds__(THREADS, 2)
void sdpa_kernel(const float* __restrict__ q,
                 float* __restrict__ out,
                 float* __restrict__ attn)
{
    extern __shared__ char smc[];
    __half* qh   = (__half*)(smc + OFF_QH);
    float*  red  = (float*)(smc + OFF_RED);
    float*  rinv = (float*)(smc + OFF_RINV);
    const unsigned sbase = (unsigned)__cvta_generic_to_shared(smc);

    const int t    = threadIdx.x;
    const int lane = t & 31;
    const int w    = t >> 5;
    const int mb   = w & 1;           // 16-row block
    const int jg   = w >> 1;          // pair id 0..7: 16-col slice per round
    const int tp   = mb * 32 + lane;  // thread index within pair (0..63)
    const int barid = jg + 1;         // named barrier 1..8 (0 reserved for CTA sync)
    const int m0   = blockIdx.x * M_TILE;
    const int h    = blockIdx.y;
    const int b    = blockIdx.z;
    const int bh   = b * HEADS + h;

    const float4* qg4 = (const float4*)(q + ((size_t)bh * T_SEQ + m0) * CDIM);
    const __half* kg  = g_k16 + ((size_t)bh * T_SEQ + jg * 16) * CDIM;   // pair's slice rows
    const __half* vg  = g_v16 + ((size_t)bh * T_SEQ + jg * 16) * CDIM;
    float* attng = attn + ((size_t)bh * T_SEQ + m0) * T_SEQ;
    float* outg  = out  + ((size_t)bh * T_SEQ + m0) * CDIM;
    __half* scoc = g_sco + ((size_t)bh * (T_SEQ / M_TILE) + blockIdx.x) * (M_TILE * T_SEQ);

    // pair-private buffer bases (bytes): K0,K1,V0,V1 each 2304 B
    const unsigned pbase = sbase + (unsigned)(jg * PAIR_BYTES);
    const unsigned kb0 = pbase, vb0 = pbase + 4608;

    // ---- prologue: stage rounds 0,1 (pair-private), load Q ----
    stage_pair(kb0,        vb0,        kg,                   vg,                   tp);
    CP_COMMIT();
    stage_pair(kb0 + 2304, vb0 + 2304, kg + KTILE * CDIM,    vg + KTILE * CDIM,    tp);
    CP_COMMIT();
    {
        int row = t >> 4, c4 = t & 15;
        float4 f = qg4[t];
        *(uint2*)&qh[row * 72 + c4 * 4] =
            make_uint2(pk2f(f.x * 0.125f, f.y * 0.125f), pk2f(f.z * 0.125f, f.w * 0.125f));
    }
    __syncthreads();   // qh visible CTA-wide

    // ---- Q A-fragments for this warp's 16-row block ----
    unsigned qa[4][4];
    {
        int rsel = lane & 15, csel = (lane >> 4) & 1;
        #pragma unroll
        for (int ks = 0; ks < 4; ks++) {
            unsigned addr = sbase + OFF_QH +
                (unsigned)((mb * 16 + rsel) * 72 + ks * 16 + csel * 8) * 2;
            ldsm_x4(qa[ks][0], qa[ks][1], qa[ks][2], qa[ks][3], addr);
        }
    }

    const int iL = lane & 7, subL = lane >> 3;
    const int gq = lane >> 2, t2 = (lane & 3) * 2;
    const int rowA = mb * 16 + gq;
    const unsigned* mwA = g_mbits + ((size_t)b * T_SEQ + m0 + rowA) * (T_SEQ / 32);
    const unsigned* mwB = mwA + 8 * (T_SEQ / 32);
    const int jgh    = jg >> 1;
    const int bpbase = (jg & 1) * 16 + t2;

    float rs0 = 0.f, rs1 = 0.f;
    float acc[8][4];
    #pragma unroll
    for (int nn = 0; nn < 8; nn++)
        #pragma unroll
        for (int d = 0; d < 4; d++) acc[nn][d] = 0.f;

    // ================= decoupled round loop (NO CTA-wide syncs) =================
    #pragma unroll 1
    for (int r = 0; r < ROUNDS; r++) {
        if (r < ROUNDS - 1) CP_WAIT1(); else CP_WAIT0();
        BARP(barid);                       // pair's buffer r ready (both warps' copies)
        const unsigned mw0 = mwA[r * 4 + jgh];
        const unsigned mw1 = mwB[r * 4 + jgh];

        const unsigned kb = kb0 + (r & 1) * 2304;
        const unsigned vb = vb0 + (r & 1) * 2304;

        // ---- S = (Q/8)K^T : warp's 16x16 tile (slice-local K rows) ----
        float d[2][4] = {{0.f,0.f,0.f,0.f},{0.f,0.f,0.f,0.f}};
        #pragma unroll
        for (int nt = 0; nt < 2; nt++) {
            unsigned bb[2][4];
            #pragma unroll
            for (int s = 0; s < 2; s++) {
                unsigned addr = kb + (unsigned)((nt * 8 + iL) * 144 + (s * 32 + subL * 8) * 2);
                ldsm_x4(bb[s][0], bb[s][1], bb[s][2], bb[s][3], addr);
            }
            mma_f16(d[nt][0], d[nt][1], d[nt][2], d[nt][3],
                    qa[0][0], qa[0][1], qa[0][2], qa[0][3], bb[0][0], bb[0][1]);
            mma_f16(d[nt][0], d[nt][1], d[nt][2], d[nt][3],
                    qa[1][0], qa[1][1], qa[1][2], qa[1][3], bb[0][2], bb[0][3]);
            mma_f16(d[nt][0], d[nt][1], d[nt][2], d[nt][3],
                    qa[2][0], qa[2][1], qa[2][2], qa[2][3], bb[1][0], bb[1][1]);
            mma_f16(d[nt][0], d[nt][1], d[nt][2], d[nt][3],
                    qa[3][0], qa[3][1], qa[3][2], qa[3][3], bb[1][2], bb[1][3]);
        }

        // ---- mask(bits) + exp + coalesced fp16 scratch store + rowsum + P frags ----
        unsigned pa[4];
        #pragma unroll
        for (int nt = 0; nt < 2; nt++) {
            const int bp = bpbase + nt * 8;
            float e0 = ((mw0 >> bp) & 1u)       ? __expf(d[nt][0]) : 0.f;
            float e1 = ((mw0 >> (bp + 1)) & 1u) ? __expf(d[nt][1]) : 0.f;
            float e2 = ((mw1 >> bp) & 1u)       ? __expf(d[nt][2]) : 0.f;
            float e3 = ((mw1 >> (bp + 1)) & 1u) ? __expf(d[nt][3]) : 0.f;
            unsigned p01 = pk2f(e0, e1), p23 = pk2f(e2, e3);
            *(uint2*)&scoc[(size_t)(((r * 16 + w) * 2 + nt) * 128) + lane * 4] =
                make_uint2(p01, p23);
            rs0 += e0 + e1;
            rs1 += e2 + e3;
            pa[nt * 2]     = p01;
            pa[nt * 2 + 1] = p23;
        }

        // ---- P @ V : 8 k16 mma into persistent acc (slice-local V rows) ----
        #pragma unroll
        for (int cb = 0; cb < 4; cb++) {
            unsigned v0, v1, v2, v3;
            unsigned addr = vb + (unsigned)((lane & 15) * 144 +
                                            (cb * 16 + ((lane >> 4) & 1) * 8) * 2);
            ldsm_x4_t(v0, v1, v2, v3, addr);
            mma_f16(acc[cb * 2][0], acc[cb * 2][1], acc[cb * 2][2], acc[cb * 2][3],
                    pa[0], pa[1], pa[2], pa[3], v0, v1);
            mma_f16(acc[cb * 2 + 1][0], acc[cb * 2 + 1][1], acc[cb * 2 + 1][2], acc[cb * 2 + 1][3],
                    pa[0], pa[1], pa[2], pa[3], v2, v3);
        }

        BARP(barid);                       // both warps done reading buffer r
        if (r + 2 < ROUNDS) {
            stage_pair(kb0 + (r & 1) * 2304, vb0 + (r & 1) * 2304,
                       kg + (size_t)(r + 2) * KTILE * CDIM,
                       vg + (size_t)(r + 2) * KTILE * CDIM, tp);
            CP_COMMIT();
        }
    }

    // ---- rowsum reduce ----
    rs0 += __shfl_xor_sync(0xffffffffu, rs0, 1);
    rs0 += __shfl_xor_sync(0xffffffffu, rs0, 2);
    rs1 += __shfl_xor_sync(0xffffffffu, rs1, 1);
    rs1 += __shfl_xor_sync(0xffffffffu, rs1, 2);
    if ((lane & 3) == 0) {
        red[w * 16 + gq]     = rs0;
        red[w * 16 + gq + 8] = rs1;
    }
    __syncthreads();   // all pairs done; red visible; pair buffers dead
    if (t < 32) {
        int mbr = t >> 4, rl = t & 15;
        float s = 0.f;
        #pragma unroll
        for (int g = 0; g < 8; g++) s += red[(g * 2 + mbr) * 16 + rl];
        rinv[t] = 1.0f / s;
    }

    // ---- out partials into smem (reuse pair-buffer region) ----
    float* part = (float*)smc;   // [8 jg][32 rows][PSTR] = 69,632 B <= 73,728
    #pragma unroll
    for (int nn = 0; nn < 8; nn++) {
        int col = nn * 8 + t2;
        *(float2*)&part[jg * (32 * PSTR) + rowA * PSTR + col] =
            make_float2(acc[nn][0], acc[nn][1]);
        *(float2*)&part[jg * (32 * PSTR) + (rowA + 8) * PSTR + col] =
            make_float2(acc[nn][2], acc[nn][3]);
    }
    __syncthreads();

    // ---- out: 32 rows x 16 c4 = 512 float4, one per thread ----
    {
        int row = t >> 4, c4 = t & 15;
        float4 s = {0.f, 0.f, 0.f, 0.f};
        #pragma unroll
        for (int g = 0; g < 8; g++) {
            float4 p = *(float4*)&part[g * (32 * PSTR) + row * PSTR + c4 * 4];
            s.x += p.x; s.y += p.y; s.z += p.z; s.w += p.w;
        }
        float ri = rinv[row];
        s.x *= ri; s.y *= ri; s.z *= ri; s.w *= ri;
        ((float4*)outg)[row * 16 + c4] = s;
    }

    // ---- attn epilogue: read scratch (L2-hot), normalize, single fp32 write ----
    {
        float4* a4 = (float4*)attng;
        #pragma unroll 4
        for (int i = 0; i < (M_TILE * T_SEQ / 4) / THREADS; i++) {   // 32
            int idx = i * THREADS + t;
            int rr = idx >> 9, cc = idx & 511;
            int c0  = cc * 4;
            int r   = c0 >> 7;
            int jgE = (c0 >> 4) & 7;
            int ntE = (c0 >> 3) & 1;
            int p0  = (c0 >> 1) & 3;
            int mbE = rr >> 4, hiE = (rr >> 3) & 1, gqE = rr & 7;
            size_t base = (size_t)(((r * 16 + (jgE * 2 + mbE)) * 2 + ntE) * 128);
            int l0 = gqE * 4 + p0;
            __half2 h0 = *(__half2*)&scoc[base + l0 * 4 + hiE * 2];
            __half2 h1 = *(__half2*)&scoc[base + (l0 + 1) * 4 + hiE * 2];
            float ri = rinv[rr];
            float2 f0 = __half22float2(h0), f1 = __half22float2(h1);
            a4[(size_t)rr * 512 + cc] =
                make_float4(f0.x * ri, f0.y * ri, f1.x * ri, f1.y * ri);
        }
    }
}

extern "C" void kernel_launch(void* const* d_in, const int* in_sizes, int n_in,
                              void* d_out, int out_size)
{
    const float* q    = (const float*)d_in[0];
    const float* k    = (const float*)d_in[1];
    const float* v    = (const float*)d_in[2];
    const int*   mask = (const int*)d_in[3];

    float* out  = (float*)d_out;                                   // [B,H,T,C]
    float* attn = out + (size_t)BATCH * HEADS * T_SEQ * CDIM;      // [B,H,T,T]

    cvt_kernel<<<KVELEMS / 4 / 512, 512>>>((const float4*)k, (const float4*)v);
    pack_mask_kernel<<<MASK_ELEMS / 512, 512>>>(mask);

    cudaFuncSetAttribute(sdpa_kernel,
                         cudaFuncAttributeMaxDynamicSharedMemorySize, SMEM_BYTES);
    dim3 grid(T_SEQ / M_TILE, HEADS, BATCH);   // (64, 16, 2)
    sdpa_kernel<<<grid, THREADS, SMEM_BYTES>>>(q, out, attn);
}